// round 1
// baseline (speedup 1.0000x reference)
#include <cuda_runtime.h>
#include <stdint.h>
#include <math.h>

// Problem constants
#define BB 8
#define NN 2048
#define DD 1024

// Scratch (static device globals -- runtime allocation is forbidden)
__device__ float g_Q[BB * NN * DD];
__device__ float g_K[BB * NN * DD];
__device__ float g_V[BB * NN * DD];
__device__ float g_Y[BB * NN * DD];
__device__ int   g_len[BB];

// ---------------------------------------------------------------------------
// Mask length: mask is a prefix mask (mask[b,i] = i < len[b], len >= N/2).
// Dtype of the serialized bool array is ambiguous; probe layout on device.
// Element [0,1] is guaranteed true:
//   1-byte bool: byte[1] != 0           -> stride-1 bytes
//   int32      : byte[1] == 0, w0 == 1  -> stride-4 ints
//   float32    : byte[1] == 0, w0 == 0x3f800000 -> floats
// ---------------------------------------------------------------------------
__global__ void mask_len_kernel(const unsigned char* __restrict__ m)
{
    const int b = blockIdx.x, tid = threadIdx.x;
    int mode;
    if (m[1] != 0) {
        mode = 0;
    } else {
        uint32_t w0 = *(const uint32_t*)m;
        mode = (w0 == 0x3f800000u) ? 2 : 1;
    }
    int cnt = 0;
    for (int i = tid; i < NN; i += 256) {
        size_t idx = (size_t)b * NN + i;
        bool t;
        if (mode == 0)      t = m[idx] != 0;
        else if (mode == 1) t = ((const int*)m)[idx] != 0;
        else                t = ((const float*)m)[idx] != 0.0f;
        cnt += t ? 1 : 0;
    }
    #pragma unroll
    for (int o = 16; o > 0; o >>= 1) cnt += __shfl_xor_sync(0xffffffffu, cnt, o);
    __shared__ int sc[8];
    if ((tid & 31) == 0) sc[tid >> 5] = cnt;
    __syncthreads();
    if (tid == 0) {
        int t = 0;
        #pragma unroll
        for (int w = 0; w < 8; w++) t += sc[w];
        g_len[b] = t;
    }
}

// ---------------------------------------------------------------------------
// tf32 tiled GEMM: C[m,n] (+= alpha *) sum_k A_l[m,k] * B_l[k,n]
//   A_KM = false: A global is (m,k) row-major, lda = row stride
//   A_KM = true : A global is (k,m) row-major (i.e. logical A transposed in mem)
//   B_KN = false: B global is (n,k) row-major (NT / weight layout)
//   B_KN = true : B global is (k,n) row-major
// CTA tile 128x64x32, 8 warps (2x4), warp tile 64x16, mma.m16n8k8 tf32.
// All dims assumed multiples of tile sizes (true for this problem).
// ---------------------------------------------------------------------------
#define BM 128
#define BN 64
#define BK 32

__device__ __forceinline__ uint32_t f2tf(float f)
{
    uint32_t r;
    asm("cvt.rna.tf32.f32 %0, %1;" : "=r"(r) : "f"(f));
    return r;
}

template <bool A_KM, bool B_KN>
__global__ void __launch_bounds__(256)
gemm_tf32(const float* __restrict__ A, const float* __restrict__ B,
          float* __restrict__ C,
          int lda, int ldb, int ldc, int K,
          long long sA, long long sB, long long sC, float alpha)
{
    __shared__ float As[BK][BM + 4];   // [k][m]
    __shared__ float Bs[BK][BN + 4];   // [k][n]

    const int tid = threadIdx.x;
    const int m0 = blockIdx.y * BM;
    const int n0 = blockIdx.x * BN;
    const float* Ab = A + (long long)blockIdx.z * sA;
    const float* Bb = B + (long long)blockIdx.z * sB;
    float* Cb = C + (long long)blockIdx.z * sC;

    const int warp = tid >> 5, lane = tid & 31;
    const int wm = warp >> 2, wn = warp & 3;     // warp grid 2 (M) x 4 (N)
    const int gr = lane >> 2, gc = lane & 3;     // groupID / threadID_in_group

    float acc[4][2][4];
    #pragma unroll
    for (int mf = 0; mf < 4; mf++)
        #pragma unroll
        for (int nf = 0; nf < 2; nf++)
            #pragma unroll
            for (int r = 0; r < 4; r++) acc[mf][nf][r] = 0.0f;

    for (int k0 = 0; k0 < K; k0 += BK) {
        // ---- stage A tile into As[k][m] ----
        if (A_KM) {
            #pragma unroll
            for (int it = 0; it < 4; ++it) {
                int e = tid + it * 256;            // 0..1023
                int k = e >> 5;
                int m4 = (e & 31) * 4;
                float4 v = *(const float4*)&Ab[(long long)(k0 + k) * lda + m0 + m4];
                *(float4*)&As[k][m4] = v;
            }
        } else {
            #pragma unroll
            for (int it = 0; it < 4; ++it) {
                int e = tid + it * 256;
                int m = e >> 3;
                int k4 = (e & 7) * 4;
                float4 v = *(const float4*)&Ab[(long long)(m0 + m) * lda + k0 + k4];
                As[k4 + 0][m] = v.x;
                As[k4 + 1][m] = v.y;
                As[k4 + 2][m] = v.z;
                As[k4 + 3][m] = v.w;
            }
        }
        // ---- stage B tile into Bs[k][n] ----
        if (B_KN) {
            #pragma unroll
            for (int it = 0; it < 2; ++it) {
                int e = tid + it * 256;            // 0..511
                int k = e >> 4;
                int n4 = (e & 15) * 4;
                float4 v = *(const float4*)&Bb[(long long)(k0 + k) * ldb + n0 + n4];
                *(float4*)&Bs[k][n4] = v;
            }
        } else {
            #pragma unroll
            for (int it = 0; it < 2; ++it) {
                int e = tid + it * 256;
                int n = e >> 3;
                int k4 = (e & 7) * 4;
                float4 v = *(const float4*)&Bb[(long long)(n0 + n) * ldb + k0 + k4];
                Bs[k4 + 0][n] = v.x;
                Bs[k4 + 1][n] = v.y;
                Bs[k4 + 2][n] = v.z;
                Bs[k4 + 3][n] = v.w;
            }
        }
        __syncthreads();

        #pragma unroll
        for (int kk = 0; kk < BK; kk += 8) {
            uint32_t a[4][4], bf[2][2];
            #pragma unroll
            for (int mf = 0; mf < 4; mf++) {
                int mb = wm * 64 + mf * 16;
                a[mf][0] = f2tf(As[kk + gc    ][mb + gr    ]);
                a[mf][1] = f2tf(As[kk + gc    ][mb + gr + 8]);
                a[mf][2] = f2tf(As[kk + gc + 4][mb + gr    ]);
                a[mf][3] = f2tf(As[kk + gc + 4][mb + gr + 8]);
            }
            #pragma unroll
            for (int nf = 0; nf < 2; nf++) {
                int nb = wn * 16 + nf * 8;
                bf[nf][0] = f2tf(Bs[kk + gc    ][nb + gr]);
                bf[nf][1] = f2tf(Bs[kk + gc + 4][nb + gr]);
            }
            #pragma unroll
            for (int mf = 0; mf < 4; mf++)
                #pragma unroll
                for (int nf = 0; nf < 2; nf++) {
                    asm volatile(
                        "mma.sync.aligned.m16n8k8.row.col.f32.tf32.tf32.f32 "
                        "{%0,%1,%2,%3},{%4,%5,%6,%7},{%8,%9},{%0,%1,%2,%3};"
                        : "+f"(acc[mf][nf][0]), "+f"(acc[mf][nf][1]),
                          "+f"(acc[mf][nf][2]), "+f"(acc[mf][nf][3])
                        : "r"(a[mf][0]), "r"(a[mf][1]), "r"(a[mf][2]), "r"(a[mf][3]),
                          "r"(bf[nf][0]), "r"(bf[nf][1]));
                }
        }
        __syncthreads();
    }

    // ---- epilogue ----
    #pragma unroll
    for (int mf = 0; mf < 4; mf++) {
        #pragma unroll
        for (int nf = 0; nf < 2; nf++) {
            int row = m0 + wm * 64 + mf * 16 + gr;
            int col = n0 + wn * 16 + nf * 8 + gc * 2;
            float2 v0 = make_float2(acc[mf][nf][0] * alpha, acc[mf][nf][1] * alpha);
            float2 v1 = make_float2(acc[mf][nf][2] * alpha, acc[mf][nf][3] * alpha);
            *(float2*)&Cb[(long long)row * ldc + col]       = v0;
            *(float2*)&Cb[(long long)(row + 8) * ldc + col] = v1;
        }
    }
}

// ---------------------------------------------------------------------------
// Masked softmax over the last axis, in place on att [B, N, N].
//   - query row i >= len[b]: all logits are NEG (equal) -> uniform 1/N exactly
//   - valid i: keys j >= len[b] get weight exactly 0 (exp(-1e9-max) underflows
//     to 0 in the fp32 reference too)
// One block per row; row stays in registers (1 read + 1 write).
// ---------------------------------------------------------------------------
__global__ void __launch_bounds__(256) softmax_kernel(float* __restrict__ att)
{
    const int b = blockIdx.y, i = blockIdx.x, tid = threadIdx.x;
    const int len = g_len[b];
    float* row = att + ((size_t)b * NN + i) * NN;

    if (i >= len) {
        const float u = 1.0f / (float)NN;
        for (int j = tid; j < NN; j += 256) row[j] = u;
        return;
    }

    float v[8];
    float mx = -3.4e38f;
    #pragma unroll
    for (int s = 0; s < 8; s++) {
        int j = tid + s * 256;
        v[s] = (j < len) ? row[j] : -3.4e38f;
        mx = fmaxf(mx, v[s]);
    }
    #pragma unroll
    for (int o = 16; o > 0; o >>= 1) mx = fmaxf(mx, __shfl_xor_sync(0xffffffffu, mx, o));
    __shared__ float sred[8];
    if ((tid & 31) == 0) sred[tid >> 5] = mx;
    __syncthreads();
    float M = sred[0];
    #pragma unroll
    for (int w = 1; w < 8; w++) M = fmaxf(M, sred[w]);

    float sum = 0.0f;
    #pragma unroll
    for (int s = 0; s < 8; s++) {
        int j = tid + s * 256;
        v[s] = (j < len) ? expf(v[s] - M) : 0.0f;
        sum += v[s];
    }
    #pragma unroll
    for (int o = 16; o > 0; o >>= 1) sum += __shfl_xor_sync(0xffffffffu, sum, o);
    __syncthreads();                       // sred reuse
    if ((tid & 31) == 0) sred[tid >> 5] = sum;
    __syncthreads();
    float S = 0.0f;
    #pragma unroll
    for (int w = 0; w < 8; w++) S += sred[w];
    const float inv = 1.0f / S;

    #pragma unroll
    for (int s = 0; s < 8; s++) {
        int j = tid + s * 256;
        row[j] = v[s] * inv;               // j >= len: v[s]==0 -> exact 0
    }
}

// ---------------------------------------------------------------------------
// Launch. Output layout: y [B,N,D] followed by att_weights [B,N,N].
// ---------------------------------------------------------------------------
extern "C" void kernel_launch(void* const* d_in, const int* in_sizes, int n_in,
                              void* d_out, int out_size)
{
    const float* x  = (const float*)d_in[0];
    const unsigned char* mask = (const unsigned char*)d_in[1];
    const float* Wq = (const float*)d_in[2];
    const float* Wk = (const float*)d_in[3];
    const float* Wv = (const float*)d_in[4];
    const float* Wo = (const float*)d_in[5];

    float* y_out = (float*)d_out;
    float* att   = (float*)d_out + (size_t)BB * NN * DD;

    void *pQ, *pK, *pV, *pY;
    cudaGetSymbolAddress(&pQ, g_Q);
    cudaGetSymbolAddress(&pK, g_K);
    cudaGetSymbolAddress(&pV, g_V);
    cudaGetSymbolAddress(&pY, g_Y);
    float* Q = (float*)pQ;
    float* Km = (float*)pK;
    float* V = (float*)pV;
    float* Y = (float*)pY;

    const dim3 blk(256);

    // 0) mask lengths
    mask_len_kernel<<<BB, 256>>>(mask);

    // 1) QKV projections: [16384,1024] x [1024,1024]^T  (A:(m,k), B:(n,k))
    {
        dim3 grid(DD / BN, (BB * NN) / BM, 1);
        gemm_tf32<false, false><<<grid, blk>>>(x, Wq, Q,  DD, DD, DD, DD, 0, 0, 0, 0.06f);
        gemm_tf32<false, false><<<grid, blk>>>(x, Wk, Km, DD, DD, DD, DD, 0, 0, 0, 1.0f);
        gemm_tf32<false, false><<<grid, blk>>>(x, Wv, V,  DD, DD, DD, DD, 0, 0, 0, 1.0f);
    }

    // 2) logits = Q @ K^T per batch: M=N=2048, K=1024  (A:(m,k), B:(n,k))
    {
        dim3 grid(NN / BN, NN / BM, BB);
        gemm_tf32<false, false><<<grid, blk>>>(
            Q, Km, att, DD, DD, NN, DD,
            (long long)NN * DD, (long long)NN * DD, (long long)NN * NN, 1.0f);
    }

    // 3) masked softmax (in place, also finalizes att_weights output)
    {
        dim3 grid(NN, BB);
        softmax_kernel<<<grid, blk>>>(att);
    }

    // 4) y = A^T @ V per batch: M=2048(i), N=1024(d), K=2048(j)
    //    A global is att[b][j][i] = (k,m) layout; B global V is (k,n) layout.
    {
        dim3 grid(DD / BN, NN / BM, BB);
        gemm_tf32<true, true><<<grid, blk>>>(
            att, V, Y, NN, DD, DD, NN,
            (long long)NN * NN, (long long)NN * DD, (long long)NN * DD, 1.0f);
    }

    // 5) output projection: out = Y @ Wo^T
    {
        dim3 grid(DD / BN, (BB * NN) / BM, 1);
        gemm_tf32<false, false><<<grid, blk>>>(Y, Wo, y_out, DD, DD, DD, DD, 0, 0, 0, 1.0f);
    }
}

// round 2
// speedup vs baseline: 1.9893x; 1.9893x over previous
#include <cuda_runtime.h>
#include <stdint.h>
#include <math.h>

// Problem constants
#define BB 8
#define NN 2048
#define DD 1024

// Scratch (static device globals -- runtime allocation is forbidden)
__device__ float g_Q[BB * NN * DD];
__device__ float g_K[BB * NN * DD];
__device__ float g_V[BB * NN * DD];
__device__ float g_Y[BB * NN * DD];
__device__ int   g_len[BB];

// ---------------------------------------------------------------------------
// Mask length probe (prefix mask, element [0,1] is always true)
// ---------------------------------------------------------------------------
__global__ void mask_len_kernel(const unsigned char* __restrict__ m)
{
    const int b = blockIdx.x, tid = threadIdx.x;
    int mode;
    if (m[1] != 0) {
        mode = 0;
    } else {
        uint32_t w0 = *(const uint32_t*)m;
        mode = (w0 == 0x3f800000u) ? 2 : 1;
    }
    int cnt = 0;
    for (int i = tid; i < NN; i += 256) {
        size_t idx = (size_t)b * NN + i;
        bool t;
        if (mode == 0)      t = m[idx] != 0;
        else if (mode == 1) t = ((const int*)m)[idx] != 0;
        else                t = ((const float*)m)[idx] != 0.0f;
        cnt += t ? 1 : 0;
    }
    #pragma unroll
    for (int o = 16; o > 0; o >>= 1) cnt += __shfl_xor_sync(0xffffffffu, cnt, o);
    __shared__ int sc[8];
    if ((tid & 31) == 0) sc[tid >> 5] = cnt;
    __syncthreads();
    if (tid == 0) {
        int t = 0;
        #pragma unroll
        for (int w = 0; w < 8; w++) t += sc[w];
        g_len[b] = t;
    }
}

// ---------------------------------------------------------------------------
// tf32 tiled GEMM, CTA tile 128x128x16, double-buffered cp.async pipeline.
// 8 warps (2 M x 4 N), warp tile 64x32, mma.m16n8k8.tf32.
//
//   A_KM=false: A gmem (m,k) k-contiguous  -> smem As[m][20]
//   A_KM=true : A gmem (k,m) m-contiguous  -> smem As[k][136]
//   B_KN=false: B gmem (n,k) k-contiguous  -> smem Bs[n][20]
//   B_KN=true : B gmem (k,n) n-contiguous  -> smem Bs[k][136]
//
// Pad strides 20 / 136 floats make every fragment LDS pattern bank-conflict
// free. All dims are multiples of tile sizes for this problem.
// ---------------------------------------------------------------------------
#define BM 128
#define BN 128
#define BK 16
#define LDK 20        // row stride (floats) for K-contiguous smem tiles
#define LDT 136       // row stride (floats) for T-contiguous smem tiles
#define SSZ 2560      // per-stage floats per operand: max(128*20, 16*136)

__device__ __forceinline__ uint32_t f2tf(float f)
{
    uint32_t r;
    asm("cvt.rna.tf32.f32 %0, %1;" : "=r"(r) : "f"(f));
    return r;
}

__device__ __forceinline__ void cpasync16(uint32_t dst, const float* src)
{
    asm volatile("cp.async.cg.shared.global [%0], [%1], 16;" :: "r"(dst), "l"(src));
}

template <bool A_KM, bool B_KN>
__global__ void __launch_bounds__(256, 2)
gemm_tf32(const float* __restrict__ A, const float* __restrict__ B,
          float* __restrict__ C,
          int lda, int ldb, int ldc, int K,
          long long sA, long long sB, long long sC, float alpha)
{
    __shared__ __align__(16) float As[2][SSZ];
    __shared__ __align__(16) float Bs[2][SSZ];

    const int tid = threadIdx.x;
    const int m0 = blockIdx.y * BM;
    const int n0 = blockIdx.x * BN;
    const float* Ab = A + (long long)blockIdx.z * sA;
    const float* Bb = B + (long long)blockIdx.z * sB;
    float* Cb = C + (long long)blockIdx.z * sC;

    const int warp = tid >> 5, lane = tid & 31;
    const int wm = warp >> 2, wn = warp & 3;   // 2 x 4 warp grid
    const int gr = lane >> 2, gc = lane & 3;   // groupID / thread-in-group

    const uint32_t sA0 = (uint32_t)__cvta_generic_to_shared(&As[0][0]);
    const uint32_t sB0 = (uint32_t)__cvta_generic_to_shared(&Bs[0][0]);

    float acc[4][4][4];
    #pragma unroll
    for (int mf = 0; mf < 4; mf++)
        #pragma unroll
        for (int nf = 0; nf < 4; nf++)
            #pragma unroll
            for (int r = 0; r < 4; r++) acc[mf][nf][r] = 0.0f;

    // ---- async staging: 512 16B chunks per operand per stage, 2/thread ----
    auto stageA = [&](int buf, int k0) {
        #pragma unroll
        for (int it = 0; it < 2; ++it) {
            int c = tid + it * 256;
            if (!A_KM) {
                int row = c >> 2, koff = (c & 3) * 4;
                cpasync16(sA0 + (uint32_t)(buf * SSZ + row * LDK + koff) * 4u,
                          Ab + (long long)(m0 + row) * lda + k0 + koff);
            } else {
                int row = c >> 5, toff = (c & 31) * 4;
                cpasync16(sA0 + (uint32_t)(buf * SSZ + row * LDT + toff) * 4u,
                          Ab + (long long)(k0 + row) * lda + m0 + toff);
            }
        }
    };
    auto stageB = [&](int buf, int k0) {
        #pragma unroll
        for (int it = 0; it < 2; ++it) {
            int c = tid + it * 256;
            if (!B_KN) {
                int row = c >> 2, koff = (c & 3) * 4;
                cpasync16(sB0 + (uint32_t)(buf * SSZ + row * LDK + koff) * 4u,
                          Bb + (long long)(n0 + row) * ldb + k0 + koff);
            } else {
                int row = c >> 5, toff = (c & 31) * 4;
                cpasync16(sB0 + (uint32_t)(buf * SSZ + row * LDT + toff) * 4u,
                          Bb + (long long)(k0 + row) * ldb + n0 + toff);
            }
        }
    };

    auto compute = [&](int buf) {
        const float* sa = &As[buf][0];
        const float* sb = &Bs[buf][0];
        #pragma unroll
        for (int kk = 0; kk < BK; kk += 8) {
            uint32_t a[4][4];
            #pragma unroll
            for (int mf = 0; mf < 4; mf++) {
                int mr = wm * 64 + mf * 16 + gr;
                if (!A_KM) {
                    a[mf][0] = f2tf(sa[(mr    ) * LDK + kk + gc    ]);
                    a[mf][1] = f2tf(sa[(mr + 8) * LDK + kk + gc    ]);
                    a[mf][2] = f2tf(sa[(mr    ) * LDK + kk + gc + 4]);
                    a[mf][3] = f2tf(sa[(mr + 8) * LDK + kk + gc + 4]);
                } else {
                    a[mf][0] = f2tf(sa[(kk + gc    ) * LDT + mr    ]);
                    a[mf][1] = f2tf(sa[(kk + gc    ) * LDT + mr + 8]);
                    a[mf][2] = f2tf(sa[(kk + gc + 4) * LDT + mr    ]);
                    a[mf][3] = f2tf(sa[(kk + gc + 4) * LDT + mr + 8]);
                }
            }
            uint32_t b[4][2];
            #pragma unroll
            for (int nf = 0; nf < 4; nf++) {
                int nc = wn * 32 + nf * 8 + gr;
                if (!B_KN) {
                    b[nf][0] = f2tf(sb[nc * LDK + kk + gc    ]);
                    b[nf][1] = f2tf(sb[nc * LDK + kk + gc + 4]);
                } else {
                    b[nf][0] = f2tf(sb[(kk + gc    ) * LDT + nc]);
                    b[nf][1] = f2tf(sb[(kk + gc + 4) * LDT + nc]);
                }
            }
            #pragma unroll
            for (int mf = 0; mf < 4; mf++)
                #pragma unroll
                for (int nf = 0; nf < 4; nf++) {
                    asm volatile(
                        "mma.sync.aligned.m16n8k8.row.col.f32.tf32.tf32.f32 "
                        "{%0,%1,%2,%3},{%4,%5,%6,%7},{%8,%9},{%0,%1,%2,%3};"
                        : "+f"(acc[mf][nf][0]), "+f"(acc[mf][nf][1]),
                          "+f"(acc[mf][nf][2]), "+f"(acc[mf][nf][3])
                        : "r"(a[mf][0]), "r"(a[mf][1]), "r"(a[mf][2]), "r"(a[mf][3]),
                          "r"(b[nf][0]), "r"(b[nf][1]));
                }
        }
    };

    // ---- pipelined main loop (2 stages) ----
    stageA(0, 0);
    stageB(0, 0);
    asm volatile("cp.async.commit_group;");
    asm volatile("cp.async.wait_group 0;");
    __syncthreads();

    int buf = 0;
    for (int k0 = 0; k0 < K; k0 += BK) {
        const bool has_next = (k0 + BK) < K;
        if (has_next) {
            stageA(buf ^ 1, k0 + BK);
            stageB(buf ^ 1, k0 + BK);
            asm volatile("cp.async.commit_group;");
        }
        compute(buf);
        if (has_next) asm volatile("cp.async.wait_group 0;");
        __syncthreads();
        buf ^= 1;
    }

    // ---- epilogue ----
    #pragma unroll
    for (int mf = 0; mf < 4; mf++) {
        #pragma unroll
        for (int nf = 0; nf < 4; nf++) {
            int row = m0 + wm * 64 + mf * 16 + gr;
            int col = n0 + wn * 32 + nf * 8 + gc * 2;
            float2 v0 = make_float2(acc[mf][nf][0] * alpha, acc[mf][nf][1] * alpha);
            float2 v1 = make_float2(acc[mf][nf][2] * alpha, acc[mf][nf][3] * alpha);
            *(float2*)&Cb[(long long)row * ldc + col]       = v0;
            *(float2*)&Cb[(long long)(row + 8) * ldc + col] = v1;
        }
    }
}

// ---------------------------------------------------------------------------
// Masked softmax over the last axis, in place on att [B, N, N].
// ---------------------------------------------------------------------------
__global__ void __launch_bounds__(256) softmax_kernel(float* __restrict__ att)
{
    const int b = blockIdx.y, i = blockIdx.x, tid = threadIdx.x;
    const int len = g_len[b];
    float* row = att + ((size_t)b * NN + i) * NN;

    if (i >= len) {
        const float u = 1.0f / (float)NN;
        for (int j = tid; j < NN; j += 256) row[j] = u;
        return;
    }

    float v[8];
    float mx = -3.4e38f;
    #pragma unroll
    for (int s = 0; s < 8; s++) {
        int j = tid + s * 256;
        v[s] = (j < len) ? row[j] : -3.4e38f;
        mx = fmaxf(mx, v[s]);
    }
    #pragma unroll
    for (int o = 16; o > 0; o >>= 1) mx = fmaxf(mx, __shfl_xor_sync(0xffffffffu, mx, o));
    __shared__ float sred[8];
    if ((tid & 31) == 0) sred[tid >> 5] = mx;
    __syncthreads();
    float M = sred[0];
    #pragma unroll
    for (int w = 1; w < 8; w++) M = fmaxf(M, sred[w]);

    float sum = 0.0f;
    #pragma unroll
    for (int s = 0; s < 8; s++) {
        int j = tid + s * 256;
        v[s] = (j < len) ? expf(v[s] - M) : 0.0f;
        sum += v[s];
    }
    #pragma unroll
    for (int o = 16; o > 0; o >>= 1) sum += __shfl_xor_sync(0xffffffffu, sum, o);
    __syncthreads();
    if ((tid & 31) == 0) sred[tid >> 5] = sum;
    __syncthreads();
    float S = 0.0f;
    #pragma unroll
    for (int w = 0; w < 8; w++) S += sred[w];
    const float inv = 1.0f / S;

    #pragma unroll
    for (int s = 0; s < 8; s++) {
        int j = tid + s * 256;
        row[j] = v[s] * inv;
    }
}

// ---------------------------------------------------------------------------
// Launch. Output layout: y [B,N,D] followed by att_weights [B,N,N].
// ---------------------------------------------------------------------------
extern "C" void kernel_launch(void* const* d_in, const int* in_sizes, int n_in,
                              void* d_out, int out_size)
{
    const float* x  = (const float*)d_in[0];
    const unsigned char* mask = (const unsigned char*)d_in[1];
    const float* Wq = (const float*)d_in[2];
    const float* Wk = (const float*)d_in[3];
    const float* Wv = (const float*)d_in[4];
    const float* Wo = (const float*)d_in[5];

    float* y_out = (float*)d_out;
    float* att   = (float*)d_out + (size_t)BB * NN * DD;

    void *pQ, *pK, *pV, *pY;
    cudaGetSymbolAddress(&pQ, g_Q);
    cudaGetSymbolAddress(&pK, g_K);
    cudaGetSymbolAddress(&pV, g_V);
    cudaGetSymbolAddress(&pY, g_Y);
    float* Q = (float*)pQ;
    float* Km = (float*)pK;
    float* V = (float*)pV;
    float* Y = (float*)pY;

    const dim3 blk(256);

    // 0) mask lengths
    mask_len_kernel<<<BB, 256>>>(mask);

    // 1) QKV projections: [16384,1024] x [1024,1024]^T (A:(m,k), B:(n,k))
    {
        dim3 grid(DD / BN, (BB * NN) / BM, 1);
        gemm_tf32<false, false><<<grid, blk>>>(x, Wq, Q,  DD, DD, DD, DD, 0, 0, 0, 0.06f);
        gemm_tf32<false, false><<<grid, blk>>>(x, Wk, Km, DD, DD, DD, DD, 0, 0, 0, 1.0f);
        gemm_tf32<false, false><<<grid, blk>>>(x, Wv, V,  DD, DD, DD, DD, 0, 0, 0, 1.0f);
    }

    // 2) logits = Q @ K^T per batch: M=N=2048, K=1024 (A:(m,k), B:(n,k))
    {
        dim3 grid(NN / BN, NN / BM, BB);
        gemm_tf32<false, false><<<grid, blk>>>(
            Q, Km, att, DD, DD, NN, DD,
            (long long)NN * DD, (long long)NN * DD, (long long)NN * NN, 1.0f);
    }

    // 3) masked softmax (in place; finalizes att_weights output)
    {
        dim3 grid(NN, BB);
        softmax_kernel<<<grid, blk>>>(att);
    }

    // 4) y = A^T @ V per batch: M=2048(i), N=1024(d), K=2048(j)
    //    att is (k,m) in memory; V is (k,n).
    {
        dim3 grid(DD / BN, NN / BM, BB);
        gemm_tf32<true, true><<<grid, blk>>>(
            att, V, Y, NN, DD, DD, NN,
            (long long)NN * NN, (long long)NN * DD, (long long)NN * DD, 1.0f);
    }

    // 5) output projection: out = Y @ Wo^T
    {
        dim3 grid(DD / BN, (BB * NN) / BM, 1);
        gemm_tf32<false, false><<<grid, blk>>>(Y, Wo, y_out, DD, DD, DD, DD, 0, 0, 0, 1.0f);
    }
}

// round 3
// speedup vs baseline: 2.5000x; 1.2567x over previous
#include <cuda_runtime.h>
#include <stdint.h>
#include <math.h>

// Problem constants
#define BB 8
#define NN 2048
#define DD 1024

// Scratch (static device globals -- runtime allocation is forbidden).
// NOTE: zero-initialized at module load; skipped (masked) Q/K rows stay 0,
// which keeps never-read logits regions finite.
__device__ float g_Q[BB * NN * DD];
__device__ float g_K[BB * NN * DD];
__device__ float g_V[BB * NN * DD];
__device__ float g_Y[BB * NN * DD];
__device__ int   g_len[BB];

// ---------------------------------------------------------------------------
// Mask length probe (prefix mask, element [0,1] is always true)
// ---------------------------------------------------------------------------
__global__ void mask_len_kernel(const unsigned char* __restrict__ m)
{
    const int b = blockIdx.x, tid = threadIdx.x;
    int mode;
    if (m[1] != 0) {
        mode = 0;
    } else {
        uint32_t w0 = *(const uint32_t*)m;
        mode = (w0 == 0x3f800000u) ? 2 : 1;
    }
    int cnt = 0;
    for (int i = tid; i < NN; i += 256) {
        size_t idx = (size_t)b * NN + i;
        bool t;
        if (mode == 0)      t = m[idx] != 0;
        else if (mode == 1) t = ((const int*)m)[idx] != 0;
        else                t = ((const float*)m)[idx] != 0.0f;
        cnt += t ? 1 : 0;
    }
    #pragma unroll
    for (int o = 16; o > 0; o >>= 1) cnt += __shfl_xor_sync(0xffffffffu, cnt, o);
    __shared__ int sc[8];
    if ((tid & 31) == 0) sc[tid >> 5] = cnt;
    __syncthreads();
    if (tid == 0) {
        int t = 0;
        #pragma unroll
        for (int w = 0; w < 8; w++) t += sc[w];
        g_len[b] = t;
    }
}

// ---------------------------------------------------------------------------
// tf32 tiled GEMM, CTA tile 128x128x16, 3-stage cp.async pipeline.
// 8 warps (2 M x 4 N), warp tile 64x32, mma.m16n8k8.tf32.
//
//   A_KM=false: A gmem (m,k) k-contiguous  -> smem As[m][20]
//   A_KM=true : A gmem (k,m) m-contiguous  -> smem As[k][136]
//   B_KN=false: B gmem (n,k) k-contiguous  -> smem Bs[n][20]
//   B_KN=true : B gmem (k,n) n-contiguous  -> smem Bs[k][136]
//
// skip_mode: 0 = none
//            1 = skip CTA if its M-tile rows are all masked (Q/K projection;
//                batch derived from global row / NN)
//            2 = skip CTA if M-tile or N-tile fully masked (logits; batch =
//                blockIdx.z). Skipped regions of att are fully overwritten
//                by the softmax kernel.
// ---------------------------------------------------------------------------
#define BM 128
#define BN 128
#define BK 16
#define LDK 20
#define LDT 136
#define SSZ 2560                    // per-stage floats per operand
#define NSTAGE 3
#define SMEM_BYTES (NSTAGE * SSZ * 2 * 4)

__device__ __forceinline__ uint32_t f2tf(float f)
{
    uint32_t r;
    asm("cvt.rna.tf32.f32 %0, %1;" : "=r"(r) : "f"(f));
    return r;
}

__device__ __forceinline__ void cpasync16(uint32_t dst, const float* src)
{
    asm volatile("cp.async.cg.shared.global [%0], [%1], 16;" :: "r"(dst), "l"(src));
}

template <bool A_KM, bool B_KN>
__global__ void __launch_bounds__(256, 2)
gemm_tf32(const float* __restrict__ A, const float* __restrict__ B,
          float* __restrict__ C,
          int lda, int ldb, int ldc, int K,
          long long sA, long long sB, long long sC, float alpha,
          int skip_mode)
{
    extern __shared__ __align__(16) float sm[];
    float* As = sm;                 // [NSTAGE][SSZ]
    float* Bs = sm + NSTAGE * SSZ;  // [NSTAGE][SSZ]

    const int m0 = blockIdx.y * BM;
    const int n0 = blockIdx.x * BN;

    if (skip_mode == 1) {
        // projection: global row m0, batch = m0/NN (BM divides NN)
        if ((m0 % NN) >= g_len[m0 / NN]) return;
    } else if (skip_mode == 2) {
        const int len = g_len[blockIdx.z];
        if (m0 >= len || n0 >= len) return;
    }

    const int tid = threadIdx.x;
    const float* Ab = A + (long long)blockIdx.z * sA;
    const float* Bb = B + (long long)blockIdx.z * sB;
    float* Cb = C + (long long)blockIdx.z * sC;

    const int warp = tid >> 5, lane = tid & 31;
    const int wm = warp >> 2, wn = warp & 3;   // 2 x 4 warp grid
    const int gr = lane >> 2, gc = lane & 3;

    const uint32_t sA0 = (uint32_t)__cvta_generic_to_shared(As);
    const uint32_t sB0 = (uint32_t)__cvta_generic_to_shared(Bs);

    float acc[4][4][4];
    #pragma unroll
    for (int mf = 0; mf < 4; mf++)
        #pragma unroll
        for (int nf = 0; nf < 4; nf++)
            #pragma unroll
            for (int r = 0; r < 4; r++) acc[mf][nf][r] = 0.0f;

    auto stage = [&](int buf, int k0) {
        #pragma unroll
        for (int it = 0; it < 2; ++it) {
            int c = tid + it * 256;
            if (!A_KM) {
                int row = c >> 2, koff = (c & 3) * 4;
                cpasync16(sA0 + (uint32_t)(buf * SSZ + row * LDK + koff) * 4u,
                          Ab + (long long)(m0 + row) * lda + k0 + koff);
            } else {
                int row = c >> 5, toff = (c & 31) * 4;
                cpasync16(sA0 + (uint32_t)(buf * SSZ + row * LDT + toff) * 4u,
                          Ab + (long long)(k0 + row) * lda + m0 + toff);
            }
        }
        #pragma unroll
        for (int it = 0; it < 2; ++it) {
            int c = tid + it * 256;
            if (!B_KN) {
                int row = c >> 2, koff = (c & 3) * 4;
                cpasync16(sB0 + (uint32_t)(buf * SSZ + row * LDK + koff) * 4u,
                          Bb + (long long)(n0 + row) * ldb + k0 + koff);
            } else {
                int row = c >> 5, toff = (c & 31) * 4;
                cpasync16(sB0 + (uint32_t)(buf * SSZ + row * LDT + toff) * 4u,
                          Bb + (long long)(k0 + row) * ldb + n0 + toff);
            }
        }
        asm volatile("cp.async.commit_group;");
    };

    auto compute = [&](int buf) {
        const float* sa = &As[buf * SSZ];
        const float* sb = &Bs[buf * SSZ];
        #pragma unroll
        for (int kk = 0; kk < BK; kk += 8) {
            uint32_t a[4][4];
            #pragma unroll
            for (int mf = 0; mf < 4; mf++) {
                int mr = wm * 64 + mf * 16 + gr;
                if (!A_KM) {
                    a[mf][0] = f2tf(sa[(mr    ) * LDK + kk + gc    ]);
                    a[mf][1] = f2tf(sa[(mr + 8) * LDK + kk + gc    ]);
                    a[mf][2] = f2tf(sa[(mr    ) * LDK + kk + gc + 4]);
                    a[mf][3] = f2tf(sa[(mr + 8) * LDK + kk + gc + 4]);
                } else {
                    a[mf][0] = f2tf(sa[(kk + gc    ) * LDT + mr    ]);
                    a[mf][1] = f2tf(sa[(kk + gc    ) * LDT + mr + 8]);
                    a[mf][2] = f2tf(sa[(kk + gc + 4) * LDT + mr    ]);
                    a[mf][3] = f2tf(sa[(kk + gc + 4) * LDT + mr + 8]);
                }
            }
            uint32_t b[4][2];
            #pragma unroll
            for (int nf = 0; nf < 4; nf++) {
                int nc = wn * 32 + nf * 8 + gr;
                if (!B_KN) {
                    b[nf][0] = f2tf(sb[nc * LDK + kk + gc    ]);
                    b[nf][1] = f2tf(sb[nc * LDK + kk + gc + 4]);
                } else {
                    b[nf][0] = f2tf(sb[(kk + gc    ) * LDT + nc]);
                    b[nf][1] = f2tf(sb[(kk + gc + 4) * LDT + nc]);
                }
            }
            #pragma unroll
            for (int mf = 0; mf < 4; mf++)
                #pragma unroll
                for (int nf = 0; nf < 4; nf++) {
                    asm volatile(
                        "mma.sync.aligned.m16n8k8.row.col.f32.tf32.tf32.f32 "
                        "{%0,%1,%2,%3},{%4,%5,%6,%7},{%8,%9},{%0,%1,%2,%3};"
                        : "+f"(acc[mf][nf][0]), "+f"(acc[mf][nf][1]),
                          "+f"(acc[mf][nf][2]), "+f"(acc[mf][nf][3])
                        : "r"(a[mf][0]), "r"(a[mf][1]), "r"(a[mf][2]), "r"(a[mf][3]),
                          "r"(b[nf][0]), "r"(b[nf][1]));
                }
        }
    };

    // ---- prologue: fill 2 of 3 stages ----
    stage(0, 0);
    stage(1, BK);
    asm volatile("cp.async.wait_group 1;");
    __syncthreads();

    int buf = 0;
    for (int k0 = 0; k0 < K; k0 += BK) {
        if (k0 + 2 * BK < K) stage((buf + 2) % NSTAGE, k0 + 2 * BK);
        compute(buf);
        if (k0 + 2 * BK < K) asm volatile("cp.async.wait_group 1;");
        else                 asm volatile("cp.async.wait_group 0;");
        __syncthreads();
        buf = (buf + 1) % NSTAGE;
    }

    // ---- epilogue ----
    #pragma unroll
    for (int mf = 0; mf < 4; mf++) {
        #pragma unroll
        for (int nf = 0; nf < 4; nf++) {
            int row = m0 + wm * 64 + mf * 16 + gr;
            int col = n0 + wn * 32 + nf * 8 + gc * 2;
            float2 v0 = make_float2(acc[mf][nf][0] * alpha, acc[mf][nf][1] * alpha);
            float2 v1 = make_float2(acc[mf][nf][2] * alpha, acc[mf][nf][3] * alpha);
            *(float2*)&Cb[(long long)row * ldc + col]       = v0;
            *(float2*)&Cb[(long long)(row + 8) * ldc + col] = v1;
        }
    }
}

// ---------------------------------------------------------------------------
// Masked softmax over the last axis, in place on att [B, N, N].
// Overwrites EVERY element (this is what makes logits tile-skipping legal).
// ---------------------------------------------------------------------------
__global__ void __launch_bounds__(256) softmax_kernel(float* __restrict__ att)
{
    const int b = blockIdx.y, i = blockIdx.x, tid = threadIdx.x;
    const int len = g_len[b];
    float* row = att + ((size_t)b * NN + i) * NN;

    if (i >= len) {
        const float u = 1.0f / (float)NN;
        for (int j = tid; j < NN; j += 256) row[j] = u;
        return;
    }

    float v[8];
    float mx = -3.4e38f;
    #pragma unroll
    for (int s = 0; s < 8; s++) {
        int j = tid + s * 256;
        v[s] = (j < len) ? row[j] : -3.4e38f;
        mx = fmaxf(mx, v[s]);
    }
    #pragma unroll
    for (int o = 16; o > 0; o >>= 1) mx = fmaxf(mx, __shfl_xor_sync(0xffffffffu, mx, o));
    __shared__ float sred[8];
    if ((tid & 31) == 0) sred[tid >> 5] = mx;
    __syncthreads();
    float M = sred[0];
    #pragma unroll
    for (int w = 1; w < 8; w++) M = fmaxf(M, sred[w]);

    float sum = 0.0f;
    #pragma unroll
    for (int s = 0; s < 8; s++) {
        int j = tid + s * 256;
        v[s] = (j < len) ? expf(v[s] - M) : 0.0f;
        sum += v[s];
    }
    #pragma unroll
    for (int o = 16; o > 0; o >>= 1) sum += __shfl_xor_sync(0xffffffffu, sum, o);
    __syncthreads();
    if ((tid & 31) == 0) sred[tid >> 5] = sum;
    __syncthreads();
    float S = 0.0f;
    #pragma unroll
    for (int w = 0; w < 8; w++) S += sred[w];
    const float inv = 1.0f / S;

    #pragma unroll
    for (int s = 0; s < 8; s++) {
        int j = tid + s * 256;
        row[j] = v[s] * inv;
    }
}

// ---------------------------------------------------------------------------
// Launch. Output layout: y [B,N,D] followed by att_weights [B,N,N].
// ---------------------------------------------------------------------------
extern "C" void kernel_launch(void* const* d_in, const int* in_sizes, int n_in,
                              void* d_out, int out_size)
{
    const float* x  = (const float*)d_in[0];
    const unsigned char* mask = (const unsigned char*)d_in[1];
    const float* Wq = (const float*)d_in[2];
    const float* Wk = (const float*)d_in[3];
    const float* Wv = (const float*)d_in[4];
    const float* Wo = (const float*)d_in[5];

    float* y_out = (float*)d_out;
    float* att   = (float*)d_out + (size_t)BB * NN * DD;

    void *pQ, *pK, *pV, *pY;
    cudaGetSymbolAddress(&pQ, g_Q);
    cudaGetSymbolAddress(&pK, g_K);
    cudaGetSymbolAddress(&pV, g_V);
    cudaGetSymbolAddress(&pY, g_Y);
    float* Q = (float*)pQ;
    float* Km = (float*)pK;
    float* V = (float*)pV;
    float* Y = (float*)pY;

    // Allow 60KB dynamic smem (attribute set is idempotent, capture-safe)
    cudaFuncSetAttribute(gemm_tf32<false, false>,
                         cudaFuncAttributeMaxDynamicSharedMemorySize, SMEM_BYTES);
    cudaFuncSetAttribute(gemm_tf32<true, true>,
                         cudaFuncAttributeMaxDynamicSharedMemorySize, SMEM_BYTES);

    const dim3 blk(256);

    // 0) mask lengths (must precede skip-enabled GEMMs)
    mask_len_kernel<<<BB, 256>>>(mask);

    // 1) QKV projections (Q,K skip masked row-tiles; V full)
    {
        dim3 grid(DD / BN, (BB * NN) / BM, 1);
        gemm_tf32<false, false><<<grid, blk, SMEM_BYTES>>>(x, Wq, Q,  DD, DD, DD, DD, 0, 0, 0, 0.06f, 1);
        gemm_tf32<false, false><<<grid, blk, SMEM_BYTES>>>(x, Wk, Km, DD, DD, DD, DD, 0, 0, 0, 1.0f, 1);
        gemm_tf32<false, false><<<grid, blk, SMEM_BYTES>>>(x, Wv, V,  DD, DD, DD, DD, 0, 0, 0, 1.0f, 0);
    }

    // 2) logits = Q @ K^T per batch (skip fully-masked tiles)
    {
        dim3 grid(NN / BN, NN / BM, BB);
        gemm_tf32<false, false><<<grid, blk, SMEM_BYTES>>>(
            Q, Km, att, DD, DD, NN, DD,
            (long long)NN * DD, (long long)NN * DD, (long long)NN * NN, 1.0f, 2);
    }

    // 3) masked softmax (in place; finalizes att_weights output)
    {
        dim3 grid(NN, BB);
        softmax_kernel<<<grid, blk>>>(att);
    }

    // 4) y = A^T @ V per batch (att is (k,m) in memory; V is (k,n)) -- full
    {
        dim3 grid(DD / BN, NN / BM, BB);
        gemm_tf32<true, true><<<grid, blk, SMEM_BYTES>>>(
            att, V, Y, NN, DD, DD, NN,
            (long long)NN * NN, (long long)NN * DD, (long long)NN * DD, 1.0f, 0);
    }

    // 5) output projection: out = Y @ Wo^T -- full
    {
        dim3 grid(DD / BN, (BB * NN) / BM, 1);
        gemm_tf32<false, false><<<grid, blk, SMEM_BYTES>>>(Y, Wo, y_out, DD, DD, DD, DD, 0, 0, 0, 1.0f, 0);
    }
}